// round 6
// baseline (speedup 1.0000x reference)
#include <cuda_runtime.h>
#include <math.h>
#include <stdint.h>

// ---------------- constants ----------------
#define NFFT   2048
#define HOP    512
#define BINS   1025
#define DMODEL 2050
#define DFF3   8200
#define BATCH  4
#define LEN    441000
#define NB     8          // BATCH*2 signals
#define TT     862        // frames
#define NM     (BATCH*TT) // 3448 transformer rows
#define NBT    (NB*TT)    // 6896 stft rows
#define HD     1025       // head dim
#define HDP    1028       // padded head dim (mult of 4)
#define TTP    864        // padded TT
#define SSQ    ((long)TT*TT)

// ---------------- workspace layout ----------------
constexpr long SZ_F1     = (long)DMODEL*NFFT;   // F1T: [DMODEL][NFFT]
constexpr long SZ_C2     = (long)NFFT*DMODEL;   // C2T: [NFFT][DMODEL]
constexpr long SZ_FRAMES = (long)NBT*NFFT;
constexpr long SZ_SPEC   = (long)NBT*DMODEL;
constexpr long SZ_X      = (long)NM*DMODEL;
constexpr long SZ_QKV    = (long)NM*3*DMODEL;
constexpr long SZ_SC     = 4L*NB*SSQ;
constexpr long SZ_CB     = 3L*NB*SSQ;
constexpr long SZ_H      = (long)NM*DFF3;
constexpr long SZ_QP     = 16L*TT*HDP;
constexpr long SZ_VT     = 16L*HDP*TTP;

constexpr long OF_F1     = 0;
constexpr long OF_C2     = OF_F1 + SZ_F1;
constexpr long OF_FRAMES = OF_C2 + SZ_C2;
constexpr long OF_SPEC   = OF_FRAMES + SZ_FRAMES;
constexpr long OF_XR     = OF_SPEC + SZ_SPEC;
constexpr long OF_XI     = OF_XR + SZ_X;
constexpr long OF_QKVR   = OF_XI + SZ_X;
constexpr long OF_QKVI   = OF_QKVR + SZ_QKV;
constexpr long OF_SC     = OF_QKVI + SZ_QKV;
constexpr long OF_CB     = OF_SC + SZ_SC;
constexpr long OF_OR     = OF_CB + SZ_CB;
constexpr long OF_OI     = OF_OR + SZ_X;
constexpr long OF_HR     = OF_OI + SZ_X;
constexpr long OF_HI     = OF_HR + SZ_H;
constexpr long OF_FR     = OF_HI + SZ_H;
constexpr long OF_FI     = OF_FR + SZ_X;
constexpr long OF_SP2    = OF_FI + SZ_X;
constexpr long OF_QP     = OF_SP2 + SZ_SPEC;
constexpr long OF_KP     = OF_QP + SZ_QP;
constexpr long OF_VT     = OF_KP + SZ_QP;
constexpr long WS_TOTAL  = OF_VT + SZ_VT;

__device__ __align__(256) float gWS[WS_TOTAL];

// ---------------- helpers ----------------
__device__ __forceinline__ unsigned totf(float x) {
    unsigned r; asm("cvt.rna.tf32.f32 %0, %1;" : "=r"(r) : "f"(x)); return r;
}
__device__ __forceinline__ void mma8(float* c, const unsigned* a, const unsigned* b) {
    asm volatile(
        "mma.sync.aligned.m16n8k8.row.col.f32.tf32.tf32.f32 "
        "{%0,%1,%2,%3},{%4,%5,%6,%7},{%8,%9},{%0,%1,%2,%3};\n"
        : "+f"(c[0]), "+f"(c[1]), "+f"(c[2]), "+f"(c[3])
        : "r"(a[0]), "r"(a[1]), "r"(a[2]), "r"(a[3]),
          "r"(b[0]), "r"(b[1]));
}

// ---------------- tf32x3 tensor GEMM, hi/lo pre-split in smem ----------------
// TB form: C[M,N] = alpha * A[M,K] @ B[N,K]^T (+bias_scale*bias) (+C) (relu)
#define TW 20                    // padded tile row width (words)
#define TILE_WORDS (128*TW)      // one 128x16 tile

__global__ void __launch_bounds__(256, 2) gemm_mma_k(
    const float* __restrict__ A, const float* __restrict__ B,
    float* __restrict__ C, const float* __restrict__ bias,
    int M, int N, int K, int lda, int ldb, int ldc,
    float alpha, float bias_scale, int accumulate, int relu,
    long sA0, long sA1, long sB0, long sB1, long sC0, long sC1)
{
    extern __shared__ unsigned smem[];
    int z = blockIdx.z;
    A += (long)(z >> 1) * sA0 + (long)(z & 1) * sA1;
    B += (long)(z >> 1) * sB0 + (long)(z & 1) * sB1;
    C += (long)(z >> 1) * sC0 + (long)(z & 1) * sC1;

    const int tid  = threadIdx.x;
    const int lane = tid & 31;
    const int warp = tid >> 5;
    const int wm   = (warp >> 2) * 64;    // 0 / 64
    const int wn   = (warp & 3) * 32;     // 0..96
    const int row0 = blockIdx.y * 128;
    const int col0 = blockIdx.x * 128;

    const int lk = (tid & 7) * 2;         // k within stage (even)
    const int lr = tid >> 3;              // 0..31

    const int SW = 4 * TILE_WORDS;        // words per stage
    unsigned* AH0 = smem;
    auto AH = [&](int s) { return AH0 + s * SW; };
    auto AL = [&](int s) { return AH0 + s * SW + TILE_WORDS; };
    auto BH = [&](int s) { return AH0 + s * SW + 2 * TILE_WORDS; };
    auto BL = [&](int s) { return AH0 + s * SW + 3 * TILE_WORDS; };

    float c[4][4][4];
#pragma unroll
    for (int i = 0; i < 4; i++)
#pragma unroll
        for (int j = 0; j < 4; j++)
#pragma unroll
            for (int q = 0; q < 4; q++) c[i][j][q] = 0.f;

    auto ld2 = [&](const float* P, int R, int ld, int gr, int gk) {
        float2 v = make_float2(0.f, 0.f);
        if (gr < R) {
            long o = (long)gr * ld + gk;
            if (gk + 1 < K) v = *(const float2*)(P + o);
            else if (gk < K) v.x = P[o];
        }
        return v;
    };
    auto stsplit = [&](unsigned* H, unsigned* L, int m, float2 v) {
        unsigned hx = totf(v.x), hy = totf(v.y);
        *(uint2*)&H[m * TW + lk] = make_uint2(hx, hy);
        *(uint2*)&L[m * TW + lk] =
            make_uint2(totf(v.x - __uint_as_float(hx)),
                       totf(v.y - __uint_as_float(hy)));
    };

    // prologue: stage 0
#pragma unroll
    for (int i = 0; i < 4; i++) {
        int m = lr + 32 * i;
        stsplit(AH(0), AL(0), m, ld2(A, M, lda, row0 + m, lk));
        stsplit(BH(0), BL(0), m, ld2(B, N, ldb, col0 + m, lk));
    }
    __syncthreads();

    int buf = 0;
    for (int k0 = 0; k0 < K; k0 += 16) {
        float2 pa[4], pb[4];
        const bool nxt = (k0 + 16 < K);
        if (nxt) {
            int kg = k0 + 16 + lk;
#pragma unroll
            for (int i = 0; i < 4; i++) {
                int m = lr + 32 * i;
                pa[i] = ld2(A, M, lda, row0 + m, kg);
                pb[i] = ld2(B, N, ldb, col0 + m, kg);
            }
        }

        const unsigned* ah_t = AH(buf);
        const unsigned* al_t = AL(buf);
        const unsigned* bh_t = BH(buf);
        const unsigned* bl_t = BL(buf);

#pragma unroll
        for (int ks = 0; ks < 2; ks++) {
            const int ra = lane >> 2;
            const int kc = ks * 8 + (lane & 3);
            unsigned bh[4][2], bl[4][2];
#pragma unroll
            for (int ni = 0; ni < 4; ni++) {
                int n = wn + ni * 8 + ra;
                bh[ni][0] = bh_t[n * TW + kc];
                bh[ni][1] = bh_t[n * TW + kc + 4];
                bl[ni][0] = bl_t[n * TW + kc];
                bl[ni][1] = bl_t[n * TW + kc + 4];
            }
#pragma unroll
            for (int mi = 0; mi < 4; mi++) {
                int r = wm + mi * 16 + ra;
                unsigned ah[4], al[4];
                ah[0] = ah_t[r * TW + kc];
                ah[1] = ah_t[(r + 8) * TW + kc];
                ah[2] = ah_t[r * TW + kc + 4];
                ah[3] = ah_t[(r + 8) * TW + kc + 4];
                al[0] = al_t[r * TW + kc];
                al[1] = al_t[(r + 8) * TW + kc];
                al[2] = al_t[r * TW + kc + 4];
                al[3] = al_t[(r + 8) * TW + kc + 4];
#pragma unroll
                for (int ni = 0; ni < 4; ni++) {
                    mma8(c[mi][ni], ah, bl[ni]);   // hi*lo
                    mma8(c[mi][ni], al, bh[ni]);   // lo*hi
                    mma8(c[mi][ni], ah, bh[ni]);   // hi*hi
                }
            }
        }

        if (nxt) {
            int b2 = buf ^ 1;
#pragma unroll
            for (int i = 0; i < 4; i++) {
                int m = lr + 32 * i;
                stsplit(AH(b2), AL(b2), m, pa[i]);
                stsplit(BH(b2), BL(b2), m, pb[i]);
            }
            __syncthreads();
            buf ^= 1;
        }
    }

    // epilogue
#pragma unroll
    for (int mi = 0; mi < 4; mi++) {
        int rbase = row0 + wm + mi * 16 + (lane >> 2);
#pragma unroll
        for (int ni = 0; ni < 4; ni++) {
            int cbase = col0 + wn + ni * 8 + 2 * (lane & 3);
#pragma unroll
            for (int q = 0; q < 4; q++) {
                int r = rbase + ((q >= 2) ? 8 : 0);
                int cc = cbase + (q & 1);
                if (r < M && cc < N) {
                    float v = alpha * c[mi][ni][q];
                    if (bias) v += bias_scale * bias[cc];
                    long o = (long)r * ldc + cc;
                    if (accumulate) v += C[o];
                    if (relu) v = fmaxf(v, 0.f);
                    C[o] = v;
                }
            }
        }
    }
}

// ---------------- DFT matrix init (TB layouts) ----------------
__global__ void init_f1t(float* __restrict__ F1) {
    long i = (long)blockIdx.x * blockDim.x + threadIdx.x;
    if (i >= SZ_F1) return;
    int j = (int)(i / NFFT), n = (int)(i % NFFT);
    int k = j >> 1;
    int m = (n * k) & (NFFT - 1);
    double a = 6.283185307179586 * (double)m / (double)NFFT;
    F1[i] = (j & 1) ? (float)(-sin(a)) : (float)cos(a);
}

__global__ void init_c2t(float* __restrict__ C2, const float* __restrict__ win) {
    long i = (long)blockIdx.x * blockDim.x + threadIdx.x;
    if (i >= SZ_C2) return;
    int n = (int)(i / DMODEL), j = (int)(i % DMODEL);
    int k = j >> 1;
    int m = (n * k) & (NFFT - 1);
    double a = 6.283185307179586 * (double)m / (double)NFFT;
    double w = (k == 0 || k == BINS - 1) ? 1.0 : 2.0;
    double v = ((j & 1) ? -sin(a) : cos(a)) * w / (double)NFFT;
    C2[i] = (float)(v * (double)win[n]);
}

// ---------------- framing (reflect pad + window) ----------------
__global__ void frames_k(float* __restrict__ Fr, const float* __restrict__ mix,
                         const float* __restrict__ win) {
    long i = (long)blockIdx.x * blockDim.x + threadIdx.x;
    if (i >= SZ_FRAMES) return;
    int n = (int)(i & (NFFT - 1));
    long st = i >> 11;
    int t = (int)(st % TT);
    int s = (int)(st / TT);
    int gi = t * HOP + n;
    int j = gi - NFFT / 2;
    if (j < 0) j = -j;
    else if (j >= LEN) j = 2 * LEN - 2 - j;
    Fr[i] = mix[(long)s * LEN + j] * win[n];
}

// ---------------- conv1x1 + pos enc ----------------
__global__ void prepx_k(float* __restrict__ Xr, float* __restrict__ Xi,
                        const float* __restrict__ Spec,
                        const float* __restrict__ c1wr, const float* __restrict__ c1br,
                        const float* __restrict__ c1wi, const float* __restrict__ c1bi) {
    long i = (long)blockIdx.x * blockDim.x + threadIdx.x;
    if (i >= SZ_X) return;
    int d = (int)(i % DMODEL);
    long bt = i / DMODEL;
    int t = (int)(bt % TT);
    int b = (int)(bt / TT);
    int k = d >> 1, c = d & 1;
    long sp = ((long)(b * 2 + c) * TT + t) * DMODEL + 2 * k;
    float re = Spec[sp], im = Spec[sp + 1];
    float wr = c1wr[c], br = c1br[c], wi = c1wi[c], bi = c1bi[c];
    float nr = (re * wr + br) - (im * wi + bi);
    float ni = (im * wr + br) + (re * wi + bi);
    double freq = exp(-(double)(2 * k) * 9.210340371976184 / 2050.0);
    double arg = (double)t * freq;
    float pe = (d & 1) ? (float)cos(arg) : (float)sin(arg);
    Xr[i] = nr + pe;
    Xi[i] = ni + pe;
}

// ---------------- repack QKV into padded per-head buffers ----------------
__global__ void repack_k(const float* __restrict__ QKVr, const float* __restrict__ QKVi,
                         float* __restrict__ Qp, float* __restrict__ Kp, float* __restrict__ Vt) {
    long i = (long)blockIdx.x * blockDim.x + threadIdx.x;
    long tot = 16L * TT * HDP;
    if (i >= tot) return;
    int d = (int)(i % HDP);
    long rem = i / HDP;
    int t = (int)(rem % TT);
    int bh = (int)((rem / TT) & 7);
    int ri = (int)(rem / (TT * 8));
    const float* src = ri ? QKVi : QKVr;
    int b = bh >> 1, h = bh & 1;
    float q = 0.f, k = 0.f, v = 0.f;
    if (d < HD) {
        long o = ((long)(b * TT + t)) * (3 * DMODEL) + h * HD + d;
        q = src[o]; k = src[o + DMODEL]; v = src[o + 2 * DMODEL];
    }
    Qp[i] = q; Kp[i] = k;
    long vo = (((long)ri * 8 + bh) * HDP + d) * TTP + t;
    Vt[vo] = v;
}

// ---------------- softmax rows of length TT ----------------
__global__ void softmax_k(float* __restrict__ S) {
    long row = blockIdx.x;
    float* p = S + row * (long)TT;
    __shared__ float red[256];
    int tid = threadIdx.x;
    float m = -1e30f;
    for (int c = tid; c < TT; c += 256) m = fmaxf(m, p[c]);
    red[tid] = m; __syncthreads();
    for (int s = 128; s > 0; s >>= 1) { if (tid < s) red[tid] = fmaxf(red[tid], red[tid + s]); __syncthreads(); }
    m = red[0];
    __syncthreads();
    float sum = 0.f;
    for (int c = tid; c < TT; c += 256) { float e = __expf(p[c] - m); p[c] = e; sum += e; }
    red[tid] = sum; __syncthreads();
    for (int s = 128; s > 0; s >>= 1) { if (tid < s) red[tid] += red[tid + s]; __syncthreads(); }
    float inv = 1.f / red[0];
    for (int c = tid; c < TT; c += 256) p[c] *= inv;
}

__global__ void combine_k(float* __restrict__ CB, const float* __restrict__ SC) {
    long i = (long)blockIdx.x * blockDim.x + threadIdx.x;
    long n = (long)NB * SSQ;
    if (i >= n) return;
    float arr = SC[i], ari = SC[i + n], air = SC[i + 2 * n], aii = SC[i + 3 * n];
    CB[i]         = arr - aii;
    CB[i + n]     = ari - air;
    CB[i + 2 * n] = ari + air;
}

__global__ void ln_k(float* __restrict__ X, const float* __restrict__ g, const float* __restrict__ b) {
    long row = blockIdx.x;
    float* p = X + row * (long)DMODEL;
    __shared__ float red[256];
    int tid = threadIdx.x;
    float s = 0.f;
    for (int c = tid; c < DMODEL; c += 256) s += p[c];
    red[tid] = s; __syncthreads();
    for (int k = 128; k > 0; k >>= 1) { if (tid < k) red[tid] += red[tid + k]; __syncthreads(); }
    float mean = red[0] / (float)DMODEL;
    __syncthreads();
    float v = 0.f;
    for (int c = tid; c < DMODEL; c += 256) { float d = p[c] - mean; v += d * d; }
    red[tid] = v; __syncthreads();
    for (int k = 128; k > 0; k >>= 1) { if (tid < k) red[tid] += red[tid + k]; __syncthreads(); }
    float inv = rsqrtf(red[0] / (float)DMODEL + 1e-5f);
    for (int c = tid; c < DMODEL; c += 256) p[c] = (p[c] - mean) * inv * g[c] + b[c];
}

__global__ void mask_k(const float* __restrict__ Fr_, const float* __restrict__ Fi_,
                       const float* __restrict__ Spec, float* __restrict__ Sp2,
                       float* __restrict__ out2,
                       const float* __restrict__ c2wr, const float* __restrict__ c2br,
                       const float* __restrict__ c2wi, const float* __restrict__ c2bi) {
    long i = (long)blockIdx.x * blockDim.x + threadIdx.x;
    long tot = (long)NB * TT * BINS;
    if (i >= tot) return;
    int k = (int)(i % BINS);
    long st = i / BINS;
    int t = (int)(st % TT);
    int s = (int)(st / TT);
    int b = s >> 1, c = s & 1;
    long xo = ((long)b * TT + t) * DMODEL + 2 * k + c;
    float nr = Fr_[xo], ni = Fi_[xo];
    float mr = (nr * c2wr[c] + c2br[c]) - (ni * c2wi[c] + c2bi[c]);
    float mi = (ni * c2wr[c] + c2br[c]) + (nr * c2wi[c] + c2bi[c]);
    long sp = ((long)s * TT + t) * DMODEL + 2 * k;
    float re = Spec[sp]     * (1.f / (1.f + __expf(-mr)));
    float im = Spec[sp + 1] * (1.f / (1.f + __expf(-mi)));
    Sp2[sp] = re; Sp2[sp + 1] = im;
    long o2 = (((long)s * BINS + k) * TT + t) * 2;
    out2[o2] = re; out2[o2 + 1] = im;
}

__global__ void ola_k(const float* __restrict__ Frm, const float* __restrict__ win,
                      float* __restrict__ out1) {
    long i = (long)blockIdx.x * blockDim.x + threadIdx.x;
    long tot = (long)NB * LEN;
    if (i >= tot) return;
    int x = (int)(i % LEN);
    int s = (int)(i / LEN);
    int gi = x + NFFT / 2;
    float acc = 0.f, wsq = 0.f;
    int tmax = gi / HOP; if (tmax > TT - 1) tmax = TT - 1;
    for (int t = tmax; t >= 0; --t) {
        int n = gi - t * HOP;
        if (n >= NFFT) break;
        acc += Frm[((long)s * TT + t) * NFFT + n];
        float w = win[n];
        wsq += w * w;
    }
    out1[i] = acc / (wsq > 1e-11f ? wsq : 1.f);
}

// ---------------- host helpers ----------------
static inline unsigned ceb(long n) { return (unsigned)((n + 255) / 256); }

#define SMEM3 (2 * 4 * TILE_WORDS * 4)   // 81920 B

static void gemm3(int Z, const float* A, const float* B, float* C, const float* bias,
                  int M, int N, int K, int lda, int ldb, int ldc,
                  float alpha, float bscale, int acc, int relu,
                  long a0 = 0, long a1 = 0, long b0 = 0, long b1 = 0, long c0 = 0, long c1 = 0)
{
    cudaFuncSetAttribute(gemm_mma_k, cudaFuncAttributeMaxDynamicSharedMemorySize, SMEM3);
    dim3 g((unsigned)((N + 127) / 128), (unsigned)((M + 127) / 128), (unsigned)Z);
    gemm_mma_k<<<g, 256, SMEM3>>>(A, B, C, bias, M, N, K, lda, ldb, ldc,
                                  alpha, bscale, acc, relu, a0, a1, b0, b1, c0, c1);
}

extern "C" void kernel_launch(void* const* d_in, const int* in_sizes, int n_in,
                              void* d_out, int out_size) {
    const float* mix        = (const float*)d_in[0];
    const float* window     = (const float*)d_in[1];
    const float* c1wr       = (const float*)d_in[2];
    const float* c1br       = (const float*)d_in[3];
    const float* c1wi       = (const float*)d_in[4];
    const float* c1bi       = (const float*)d_in[5];
    const float* c2wr       = (const float*)d_in[6];
    const float* c2br       = (const float*)d_in[7];
    const float* c2wi       = (const float*)d_in[8];
    const float* c2bi       = (const float*)d_in[9];
    const float* attn_in_w  = (const float*)d_in[10];
    const float* attn_in_b  = (const float*)d_in[11];
    const float* attn_out_w = (const float*)d_in[12];
    const float* attn_out_b = (const float*)d_in[13];
    const float* l1wr       = (const float*)d_in[14];
    const float* l1br       = (const float*)d_in[15];
    const float* l1wi       = (const float*)d_in[16];
    const float* l1bi       = (const float*)d_in[17];
    const float* l2wr       = (const float*)d_in[18];
    const float* l2br       = (const float*)d_in[19];
    const float* l2wi       = (const float*)d_in[20];
    const float* l2bi       = (const float*)d_in[21];
    const float* n1_gr      = (const float*)d_in[22];
    const float* n1_br      = (const float*)d_in[23];
    const float* n1_gi      = (const float*)d_in[24];
    const float* n1_bi      = (const float*)d_in[25];
    const float* n2_gr      = (const float*)d_in[26];
    const float* n2_br      = (const float*)d_in[27];
    const float* n2_gi      = (const float*)d_in[28];
    const float* n2_bi      = (const float*)d_in[29];

    float* out = (float*)d_out;
    float* out1 = out;
    float* out2 = out + (long)NB * LEN;

    float* W = nullptr;
    cudaGetSymbolAddress((void**)&W, gWS);

    float* F1T  = W + OF_F1;
    float* C2T  = W + OF_C2;
    float* FRM  = W + OF_FRAMES;
    float* SPEC = W + OF_SPEC;
    float* XR   = W + OF_XR;
    float* XI   = W + OF_XI;
    float* QKVR = W + OF_QKVR;
    float* QKVI = W + OF_QKVI;
    float* SC   = W + OF_SC;
    float* CB   = W + OF_CB;
    float* ORr  = W + OF_OR;
    float* OIi  = W + OF_OI;
    float* HR   = W + OF_HR;
    float* HI   = W + OF_HI;
    float* FRr  = W + OF_FR;
    float* FIi  = W + OF_FI;
    float* SP2  = W + OF_SP2;
    float* QP   = W + OF_QP;
    float* KP   = W + OF_KP;
    float* VT   = W + OF_VT;

    init_f1t<<<ceb(SZ_F1), 256>>>(F1T);
    init_c2t<<<ceb(SZ_C2), 256>>>(C2T, window);

    // STFT: SPEC[m][j] = sum_n FRM[m][n] * F1T[j][n]
    frames_k<<<ceb(SZ_FRAMES), 256>>>(FRM, mix, window);
    gemm3(1, FRM, F1T, SPEC, nullptr, NBT, DMODEL, NFFT, NFFT, NFFT, DMODEL, 1.f, 0.f, 0, 0);

    prepx_k<<<ceb(SZ_X), 256>>>(XR, XI, SPEC, c1wr, c1br, c1wi, c1bi);

    // QKV
    gemm3(1, XR, attn_in_w, QKVR, attn_in_b, NM, 3 * DMODEL, DMODEL, DMODEL, DMODEL, 3 * DMODEL, 1.f, 1.f, 0, 0);
    gemm3(1, XI, attn_in_w, QKVI, attn_in_b, NM, 3 * DMODEL, DMODEL, DMODEL, DMODEL, 3 * DMODEL, 1.f, 1.f, 0, 0);

    repack_k<<<ceb(16L * TT * HDP), 256>>>(QKVR, QKVI, QP, KP, VT);

    // scores (tf32x3 — softmax IS sensitive to logit error; round-5 lesson)
    const float scl = 1.f / sqrtf((float)HD);
    const long sQ = (long)TT * HDP;
    const long sV = (long)HDP * TTP;
    const long nbs = (long)NB * SSQ;
    const float* QPr = QP; const float* QPi = QP + 8 * sQ;
    const float* KPr = KP; const float* KPi = KP + 8 * sQ;
    const float* VTr = VT; const float* VTi = VT + 8 * sV;
    gemm3(8, QPr, KPr, SC + 0 * nbs, nullptr, TT, TT, HD, HDP, HDP, TT, scl, 0.f, 0, 0, 2 * sQ, sQ, 2 * sQ, sQ, 2 * SSQ, SSQ);
    gemm3(8, QPr, KPi, SC + 1 * nbs, nullptr, TT, TT, HD, HDP, HDP, TT, scl, 0.f, 0, 0, 2 * sQ, sQ, 2 * sQ, sQ, 2 * SSQ, SSQ);
    gemm3(8, QPi, KPr, SC + 2 * nbs, nullptr, TT, TT, HD, HDP, HDP, TT, scl, 0.f, 0, 0, 2 * sQ, sQ, 2 * sQ, sQ, 2 * SSQ, SSQ);
    gemm3(8, QPi, KPi, SC + 3 * nbs, nullptr, TT, TT, HD, HDP, HDP, TT, scl, 0.f, 0, 0, 2 * sQ, sQ, 2 * sQ, sQ, 2 * SSQ, SSQ);

    softmax_k<<<4 * NB * TT, 256>>>(SC);
    combine_k<<<ceb(nbs), 256>>>(CB, SC);

    // AV: out_r = P@Vr + Q1@Vi ; out_i = P@Vi + Q2@Vr
    const long sCb = (long)TT * DMODEL, sCh = HD;
    gemm3(8, CB + 0 * nbs, VTr, XR, nullptr, TT, HD, TT, TT, TTP, DMODEL, 1.f, 0.f, 0, 0, 2 * SSQ, SSQ, 2 * sV, sV, sCb, sCh);
    gemm3(8, CB + 1 * nbs, VTi, XR, nullptr, TT, HD, TT, TT, TTP, DMODEL, 1.f, 0.f, 1, 0, 2 * SSQ, SSQ, 2 * sV, sV, sCb, sCh);
    gemm3(8, CB + 0 * nbs, VTi, XI, nullptr, TT, HD, TT, TT, TTP, DMODEL, 1.f, 0.f, 0, 0, 2 * SSQ, SSQ, 2 * sV, sV, sCb, sCh);
    gemm3(8, CB + 2 * nbs, VTr, XI, nullptr, TT, HD, TT, TT, TTP, DMODEL, 1.f, 0.f, 1, 0, 2 * SSQ, SSQ, 2 * sV, sV, sCb, sCh);

    // output projection
    gemm3(1, XR, attn_out_w, ORr, nullptr,    NM, DMODEL, DMODEL, DMODEL, DMODEL, DMODEL, 1.f, 0.f, 0, 0);
    gemm3(1, XI, attn_out_w, OIi, attn_out_b, NM, DMODEL, DMODEL, DMODEL, DMODEL, DMODEL, 1.f, 2.f, 0, 0);

    ln_k<<<NM, 256>>>(ORr, n1_gr, n1_br);
    ln_k<<<NM, 256>>>(OIi, n1_gi, n1_bi);

    // FFN layer 1 (+fused relu on accumulating second pass)
    gemm3(1, ORr, l1wr, HR, l1br, NM, DFF3, DMODEL, DMODEL, DMODEL, DFF3,  1.f,  1.f, 0, 0);
    gemm3(1, OIi, l1wi, HR, l1bi, NM, DFF3, DMODEL, DMODEL, DMODEL, DFF3, -1.f, -1.f, 1, 1);
    gemm3(1, OIi, l1wr, HI, l1br, NM, DFF3, DMODEL, DMODEL, DMODEL, DFF3,  1.f,  1.f, 0, 0);
    gemm3(1, ORr, l1wi, HI, l1bi, NM, DFF3, DMODEL, DMODEL, DMODEL, DFF3,  1.f,  1.f, 1, 1);

    // FFN layer 2
    gemm3(1, HR, l2wr, FRr, l2br, NM, DMODEL, DFF3, DFF3, DFF3, DMODEL,  1.f,  1.f, 0, 0);
    gemm3(1, HI, l2wi, FRr, l2bi, NM, DMODEL, DFF3, DFF3, DFF3, DMODEL, -1.f, -1.f, 1, 0);
    gemm3(1, HI, l2wr, FIi, l2br, NM, DMODEL, DFF3, DFF3, DFF3, DMODEL,  1.f,  1.f, 0, 0);
    gemm3(1, HR, l2wi, FIi, l2bi, NM, DMODEL, DFF3, DFF3, DFF3, DMODEL,  1.f,  1.f, 1, 0);

    ln_k<<<NM, 256>>>(FRr, n2_gr, n2_br);
    ln_k<<<NM, 256>>>(FIi, n2_gi, n2_bi);

    mask_k<<<ceb((long)NB * TT * BINS), 256>>>(FRr, FIi, SPEC, SP2, out2, c2wr, c2br, c2wi, c2bi);

    // iSTFT: FRM[m][n] = sum_j SP2[m][j] * C2T[n][j]
    gemm3(1, SP2, C2T, FRM, nullptr, NBT, NFFT, DMODEL, DMODEL, DMODEL, NFFT, 1.f, 0.f, 0, 0);
    ola_k<<<ceb((long)NB * LEN), 256>>>(FRM, window, out1);
}

// round 7
// speedup vs baseline: 1.4880x; 1.4880x over previous
#include <cuda_runtime.h>
#include <math.h>
#include <stdint.h>

// ---------------- constants ----------------
#define NFFT   2048
#define HOP    512
#define BINS   1025
#define DMODEL 2050
#define DFF3   8200
#define BATCH  4
#define LEN    441000
#define NB     8          // BATCH*2 signals
#define TT     862        // frames
#define NM     (BATCH*TT) // 3448 transformer rows
#define NBT    (NB*TT)    // 6896 stft rows
#define HD     1025       // head dim
#define HDP    1028       // padded head dim (mult of 4)
#define TTP    864        // padded TT
#define SSQ    ((long)TT*TT)

// ---------------- workspace layout ----------------
constexpr long SZ_F1     = (long)DMODEL*NFFT;   // F1T: [DMODEL][NFFT]
constexpr long SZ_C2     = (long)NFFT*DMODEL;   // C2T: [NFFT][DMODEL]
constexpr long SZ_FRAMES = (long)NBT*NFFT;
constexpr long SZ_SPEC   = (long)NBT*DMODEL;
constexpr long SZ_X      = (long)NM*DMODEL;
constexpr long SZ_QKV    = (long)NM*3*DMODEL;
constexpr long SZ_SC     = 4L*NB*SSQ;
constexpr long SZ_CB     = 3L*NB*SSQ;
constexpr long SZ_H      = (long)NM*DFF3;
constexpr long SZ_QP     = 16L*TT*HDP;
constexpr long SZ_VT     = 16L*HDP*TTP;

constexpr long OF_F1     = 0;
constexpr long OF_C2     = OF_F1 + SZ_F1;
constexpr long OF_FRAMES = OF_C2 + SZ_C2;
constexpr long OF_SPEC   = OF_FRAMES + SZ_FRAMES;
constexpr long OF_XR     = OF_SPEC + SZ_SPEC;
constexpr long OF_XI     = OF_XR + SZ_X;
constexpr long OF_QKVR   = OF_XI + SZ_X;
constexpr long OF_QKVI   = OF_QKVR + SZ_QKV;
constexpr long OF_SC     = OF_QKVI + SZ_QKV;
constexpr long OF_CB     = OF_SC + SZ_SC;
constexpr long OF_OR     = OF_CB + SZ_CB;
constexpr long OF_OI     = OF_OR + SZ_X;
constexpr long OF_HR     = OF_OI + SZ_X;
constexpr long OF_HI     = OF_HR + SZ_H;
constexpr long OF_FR     = OF_HI + SZ_H;
constexpr long OF_FI     = OF_FR + SZ_X;
constexpr long OF_SP2    = OF_FI + SZ_X;
constexpr long OF_QP     = OF_SP2 + SZ_SPEC;
constexpr long OF_KP     = OF_QP + SZ_QP;
constexpr long OF_VT     = OF_KP + SZ_QP;
constexpr long WS_TOTAL  = OF_VT + SZ_VT;

__device__ __align__(256) float gWS[WS_TOTAL];

// ---------------- helpers ----------------
__device__ __forceinline__ void mma8(float* c, const unsigned* a, const unsigned* b) {
    asm volatile(
        "mma.sync.aligned.m16n8k8.row.col.f32.tf32.tf32.f32 "
        "{%0,%1,%2,%3},{%4,%5,%6,%7},{%8,%9},{%0,%1,%2,%3};\n"
        : "+f"(c[0]), "+f"(c[1]), "+f"(c[2]), "+f"(c[3])
        : "r"(a[0]), "r"(a[1]), "r"(a[2]), "r"(a[3]),
          "r"(b[0]), "r"(b[1]));
}

// hi = x with low 13 mantissa bits zeroed (valid tf32, 1 LOP3);
// lo = x - hi (exact FADD; HW mma truncates lo's low bits -> ~2^-21 rel err)
#define TFMASK 0xFFFFE000u

// ---------------- tf32x3 tensor GEMM (raw-fp32 smem, mask-split in regs) ----
// TB form: C[M,N] = alpha * A[M,K] @ B[N,K]^T (+bias_scale*bias) (+C) (relu)
#define TW 20                    // padded tile row width (words)

__global__ void __launch_bounds__(256, 2) gemm_mma_k(
    const float* __restrict__ A, const float* __restrict__ B,
    float* __restrict__ C, const float* __restrict__ bias,
    int M, int N, int K, int lda, int ldb, int ldc,
    float alpha, float bias_scale, int accumulate, int relu,
    long sA0, long sA1, long sB0, long sB1, long sC0, long sC1)
{
    __shared__ float As[2][128][TW];
    __shared__ float Bs[2][128][TW];

    int z = blockIdx.z;
    A += (long)(z >> 1) * sA0 + (long)(z & 1) * sA1;
    B += (long)(z >> 1) * sB0 + (long)(z & 1) * sB1;
    C += (long)(z >> 1) * sC0 + (long)(z & 1) * sC1;

    const int tid  = threadIdx.x;
    const int lane = tid & 31;
    const int warp = tid >> 5;
    const int wm   = (warp >> 2) * 64;    // 0 / 64
    const int wn   = (warp & 3) * 32;     // 0..96
    const int row0 = blockIdx.y * 128;
    const int col0 = blockIdx.x * 128;

    const int lk = (tid & 7) * 2;         // k within stage (even)
    const int lr = tid >> 3;              // 0..31

    float c[4][4][4];
#pragma unroll
    for (int i = 0; i < 4; i++)
#pragma unroll
        for (int j = 0; j < 4; j++)
#pragma unroll
            for (int q = 0; q < 4; q++) c[i][j][q] = 0.f;

    auto ld2 = [&](const float* P, int R, int ld, int gr, int gk) {
        float2 v = make_float2(0.f, 0.f);
        if (gr < R) {
            long o = (long)gr * ld + gk;
            if (gk + 1 < K) v = *(const float2*)(P + o);
            else if (gk < K) v.x = P[o];
        }
        return v;
    };

    // prologue: stage 0
#pragma unroll
    for (int i = 0; i < 4; i++) {
        int m = lr + 32 * i;
        *(float2*)&As[0][m][lk] = ld2(A, M, lda, row0 + m, lk);
        *(float2*)&Bs[0][m][lk] = ld2(B, N, ldb, col0 + m, lk);
    }
    __syncthreads();

    int buf = 0;
    for (int k0 = 0; k0 < K; k0 += 16) {
        float2 pa[4], pb[4];
        const bool nxt = (k0 + 16 < K);
        if (nxt) {
            int kg = k0 + 16 + lk;
#pragma unroll
            for (int i = 0; i < 4; i++) {
                int m = lr + 32 * i;
                pa[i] = ld2(A, M, lda, row0 + m, kg);
                pb[i] = ld2(B, N, ldb, col0 + m, kg);
            }
        }

#pragma unroll
        for (int ks = 0; ks < 2; ks++) {
            const int ra = lane >> 2;
            const int kc = ks * 8 + (lane & 3);
            unsigned bh[4][2], bl[4][2];
#pragma unroll
            for (int ni = 0; ni < 4; ni++) {
                int n = wn + ni * 8 + ra;
                float b0 = Bs[buf][n][kc];
                float b1 = Bs[buf][n][kc + 4];
                unsigned h0 = __float_as_uint(b0) & TFMASK;
                unsigned h1 = __float_as_uint(b1) & TFMASK;
                bh[ni][0] = h0;
                bh[ni][1] = h1;
                bl[ni][0] = __float_as_uint(b0 - __uint_as_float(h0));
                bl[ni][1] = __float_as_uint(b1 - __uint_as_float(h1));
            }
#pragma unroll
            for (int mi = 0; mi < 4; mi++) {
                int r = wm + mi * 16 + ra;
                float a0 = As[buf][r][kc];
                float a1 = As[buf][r + 8][kc];
                float a2 = As[buf][r][kc + 4];
                float a3 = As[buf][r + 8][kc + 4];
                unsigned ah[4], al[4];
                ah[0] = __float_as_uint(a0) & TFMASK;
                ah[1] = __float_as_uint(a1) & TFMASK;
                ah[2] = __float_as_uint(a2) & TFMASK;
                ah[3] = __float_as_uint(a3) & TFMASK;
                al[0] = __float_as_uint(a0 - __uint_as_float(ah[0]));
                al[1] = __float_as_uint(a1 - __uint_as_float(ah[1]));
                al[2] = __float_as_uint(a2 - __uint_as_float(ah[2]));
                al[3] = __float_as_uint(a3 - __uint_as_float(ah[3]));
#pragma unroll
                for (int ni = 0; ni < 4; ni++) {
                    mma8(c[mi][ni], ah, bl[ni]);   // hi*lo
                    mma8(c[mi][ni], al, bh[ni]);   // lo*hi
                    mma8(c[mi][ni], ah, bh[ni]);   // hi*hi
                }
            }
        }

        if (nxt) {
            int b2 = buf ^ 1;
#pragma unroll
            for (int i = 0; i < 4; i++) {
                int m = lr + 32 * i;
                *(float2*)&As[b2][m][lk] = pa[i];
                *(float2*)&Bs[b2][m][lk] = pb[i];
            }
            __syncthreads();
            buf ^= 1;
        }
    }

    // epilogue
#pragma unroll
    for (int mi = 0; mi < 4; mi++) {
        int rbase = row0 + wm + mi * 16 + (lane >> 2);
#pragma unroll
        for (int ni = 0; ni < 4; ni++) {
            int cbase = col0 + wn + ni * 8 + 2 * (lane & 3);
#pragma unroll
            for (int q = 0; q < 4; q++) {
                int r = rbase + ((q >= 2) ? 8 : 0);
                int cc = cbase + (q & 1);
                if (r < M && cc < N) {
                    float v = alpha * c[mi][ni][q];
                    if (bias) v += bias_scale * bias[cc];
                    long o = (long)r * ldc + cc;
                    if (accumulate) v += C[o];
                    if (relu) v = fmaxf(v, 0.f);
                    C[o] = v;
                }
            }
        }
    }
}

// ---------------- DFT matrix init (TB layouts) ----------------
__global__ void init_f1t(float* __restrict__ F1) {
    long i = (long)blockIdx.x * blockDim.x + threadIdx.x;
    if (i >= SZ_F1) return;
    int j = (int)(i / NFFT), n = (int)(i % NFFT);
    int k = j >> 1;
    int m = (n * k) & (NFFT - 1);
    double a = 6.283185307179586 * (double)m / (double)NFFT;
    F1[i] = (j & 1) ? (float)(-sin(a)) : (float)cos(a);
}

__global__ void init_c2t(float* __restrict__ C2, const float* __restrict__ win) {
    long i = (long)blockIdx.x * blockDim.x + threadIdx.x;
    if (i >= SZ_C2) return;
    int n = (int)(i / DMODEL), j = (int)(i % DMODEL);
    int k = j >> 1;
    int m = (n * k) & (NFFT - 1);
    double a = 6.283185307179586 * (double)m / (double)NFFT;
    double w = (k == 0 || k == BINS - 1) ? 1.0 : 2.0;
    double v = ((j & 1) ? -sin(a) : cos(a)) * w / (double)NFFT;
    C2[i] = (float)(v * (double)win[n]);
}

// ---------------- framing (reflect pad + window) ----------------
__global__ void frames_k(float* __restrict__ Fr, const float* __restrict__ mix,
                         const float* __restrict__ win) {
    long i = (long)blockIdx.x * blockDim.x + threadIdx.x;
    if (i >= SZ_FRAMES) return;
    int n = (int)(i & (NFFT - 1));
    long st = i >> 11;
    int t = (int)(st % TT);
    int s = (int)(st / TT);
    int gi = t * HOP + n;
    int j = gi - NFFT / 2;
    if (j < 0) j = -j;
    else if (j >= LEN) j = 2 * LEN - 2 - j;
    Fr[i] = mix[(long)s * LEN + j] * win[n];
}

// ---------------- conv1x1 + pos enc ----------------
__global__ void prepx_k(float* __restrict__ Xr, float* __restrict__ Xi,
                        const float* __restrict__ Spec,
                        const float* __restrict__ c1wr, const float* __restrict__ c1br,
                        const float* __restrict__ c1wi, const float* __restrict__ c1bi) {
    long i = (long)blockIdx.x * blockDim.x + threadIdx.x;
    if (i >= SZ_X) return;
    int d = (int)(i % DMODEL);
    long bt = i / DMODEL;
    int t = (int)(bt % TT);
    int b = (int)(bt / TT);
    int k = d >> 1, c = d & 1;
    long sp = ((long)(b * 2 + c) * TT + t) * DMODEL + 2 * k;
    float re = Spec[sp], im = Spec[sp + 1];
    float wr = c1wr[c], br = c1br[c], wi = c1wi[c], bi = c1bi[c];
    float nr = (re * wr + br) - (im * wi + bi);
    float ni = (im * wr + br) + (re * wi + bi);
    double freq = exp(-(double)(2 * k) * 9.210340371976184 / 2050.0);
    double arg = (double)t * freq;
    float pe = (d & 1) ? (float)cos(arg) : (float)sin(arg);
    Xr[i] = nr + pe;
    Xi[i] = ni + pe;
}

// ---------------- repack QKV into padded per-head buffers ----------------
__global__ void repack_k(const float* __restrict__ QKVr, const float* __restrict__ QKVi,
                         float* __restrict__ Qp, float* __restrict__ Kp, float* __restrict__ Vt) {
    long i = (long)blockIdx.x * blockDim.x + threadIdx.x;
    long tot = 16L * TT * HDP;
    if (i >= tot) return;
    int d = (int)(i % HDP);
    long rem = i / HDP;
    int t = (int)(rem % TT);
    int bh = (int)((rem / TT) & 7);
    int ri = (int)(rem / (TT * 8));
    const float* src = ri ? QKVi : QKVr;
    int b = bh >> 1, h = bh & 1;
    float q = 0.f, k = 0.f, v = 0.f;
    if (d < HD) {
        long o = ((long)(b * TT + t)) * (3 * DMODEL) + h * HD + d;
        q = src[o]; k = src[o + DMODEL]; v = src[o + 2 * DMODEL];
    }
    Qp[i] = q; Kp[i] = k;
    long vo = (((long)ri * 8 + bh) * HDP + d) * TTP + t;
    Vt[vo] = v;
}

// ---------------- softmax rows of length TT ----------------
__global__ void softmax_k(float* __restrict__ S) {
    long row = blockIdx.x;
    float* p = S + row * (long)TT;
    __shared__ float red[256];
    int tid = threadIdx.x;
    float m = -1e30f;
    for (int c = tid; c < TT; c += 256) m = fmaxf(m, p[c]);
    red[tid] = m; __syncthreads();
    for (int s = 128; s > 0; s >>= 1) { if (tid < s) red[tid] = fmaxf(red[tid], red[tid + s]); __syncthreads(); }
    m = red[0];
    __syncthreads();
    float sum = 0.f;
    for (int c = tid; c < TT; c += 256) { float e = __expf(p[c] - m); p[c] = e; sum += e; }
    red[tid] = sum; __syncthreads();
    for (int s = 128; s > 0; s >>= 1) { if (tid < s) red[tid] += red[tid + s]; __syncthreads(); }
    float inv = 1.f / red[0];
    for (int c = tid; c < TT; c += 256) p[c] *= inv;
}

__global__ void combine_k(float* __restrict__ CB, const float* __restrict__ SC) {
    long i = (long)blockIdx.x * blockDim.x + threadIdx.x;
    long n = (long)NB * SSQ;
    if (i >= n) return;
    float arr = SC[i], ari = SC[i + n], air = SC[i + 2 * n], aii = SC[i + 3 * n];
    CB[i]         = arr - aii;
    CB[i + n]     = ari - air;
    CB[i + 2 * n] = ari + air;
}

__global__ void ln_k(float* __restrict__ X, const float* __restrict__ g, const float* __restrict__ b) {
    long row = blockIdx.x;
    float* p = X + row * (long)DMODEL;
    __shared__ float red[256];
    int tid = threadIdx.x;
    float s = 0.f;
    for (int c = tid; c < DMODEL; c += 256) s += p[c];
    red[tid] = s; __syncthreads();
    for (int k = 128; k > 0; k >>= 1) { if (tid < k) red[tid] += red[tid + k]; __syncthreads(); }
    float mean = red[0] / (float)DMODEL;
    __syncthreads();
    float v = 0.f;
    for (int c = tid; c < DMODEL; c += 256) { float d = p[c] - mean; v += d * d; }
    red[tid] = v; __syncthreads();
    for (int k = 128; k > 0; k >>= 1) { if (tid < k) red[tid] += red[tid + k]; __syncthreads(); }
    float inv = rsqrtf(red[0] / (float)DMODEL + 1e-5f);
    for (int c = tid; c < DMODEL; c += 256) p[c] = (p[c] - mean) * inv * g[c] + b[c];
}

__global__ void mask_k(const float* __restrict__ Fr_, const float* __restrict__ Fi_,
                       const float* __restrict__ Spec, float* __restrict__ Sp2,
                       float* __restrict__ out2,
                       const float* __restrict__ c2wr, const float* __restrict__ c2br,
                       const float* __restrict__ c2wi, const float* __restrict__ c2bi) {
    long i = (long)blockIdx.x * blockDim.x + threadIdx.x;
    long tot = (long)NB * TT * BINS;
    if (i >= tot) return;
    int k = (int)(i % BINS);
    long st = i / BINS;
    int t = (int)(st % TT);
    int s = (int)(st / TT);
    int b = s >> 1, c = s & 1;
    long xo = ((long)b * TT + t) * DMODEL + 2 * k + c;
    float nr = Fr_[xo], ni = Fi_[xo];
    float mr = (nr * c2wr[c] + c2br[c]) - (ni * c2wi[c] + c2bi[c]);
    float mi = (ni * c2wr[c] + c2br[c]) + (nr * c2wi[c] + c2bi[c]);
    long sp = ((long)s * TT + t) * DMODEL + 2 * k;
    float re = Spec[sp]     * (1.f / (1.f + __expf(-mr)));
    float im = Spec[sp + 1] * (1.f / (1.f + __expf(-mi)));
    Sp2[sp] = re; Sp2[sp + 1] = im;
    long o2 = (((long)s * BINS + k) * TT + t) * 2;
    out2[o2] = re; out2[o2 + 1] = im;
}

__global__ void ola_k(const float* __restrict__ Frm, const float* __restrict__ win,
                      float* __restrict__ out1) {
    long i = (long)blockIdx.x * blockDim.x + threadIdx.x;
    long tot = (long)NB * LEN;
    if (i >= tot) return;
    int x = (int)(i % LEN);
    int s = (int)(i / LEN);
    int gi = x + NFFT / 2;
    float acc = 0.f, wsq = 0.f;
    int tmax = gi / HOP; if (tmax > TT - 1) tmax = TT - 1;
    for (int t = tmax; t >= 0; --t) {
        int n = gi - t * HOP;
        if (n >= NFFT) break;
        acc += Frm[((long)s * TT + t) * NFFT + n];
        float w = win[n];
        wsq += w * w;
    }
    out1[i] = acc / (wsq > 1e-11f ? wsq : 1.f);
}

// ---------------- host helpers ----------------
static inline unsigned ceb(long n) { return (unsigned)((n + 255) / 256); }

static void gemm3(int Z, const float* A, const float* B, float* C, const float* bias,
                  int M, int N, int K, int lda, int ldb, int ldc,
                  float alpha, float bscale, int acc, int relu,
                  long a0 = 0, long a1 = 0, long b0 = 0, long b1 = 0, long c0 = 0, long c1 = 0)
{
    dim3 g((unsigned)((N + 127) / 128), (unsigned)((M + 127) / 128), (unsigned)Z);
    gemm_mma_k<<<g, 256>>>(A, B, C, bias, M, N, K, lda, ldb, ldc,
                           alpha, bscale, acc, relu, a0, a1, b0, b1, c0, c1);
}

extern "C" void kernel_launch(void* const* d_in, const int* in_sizes, int n_in,
                              void* d_out, int out_size) {
    const float* mix        = (const float*)d_in[0];
    const float* window     = (const float*)d_in[1];
    const float* c1wr       = (const float*)d_in[2];
    const float* c1br       = (const float*)d_in[3];
    const float* c1wi       = (const float*)d_in[4];
    const float* c1bi       = (const float*)d_in[5];
    const float* c2wr       = (const float*)d_in[6];
    const float* c2br       = (const float*)d_in[7];
    const float* c2wi       = (const float*)d_in[8];
    const float* c2bi       = (const float*)d_in[9];
    const float* attn_in_w  = (const float*)d_in[10];
    const float* attn_in_b  = (const float*)d_in[11];
    const float* attn_out_w = (const float*)d_in[12];
    const float* attn_out_b = (const float*)d_in[13];
    const float* l1wr       = (const float*)d_in[14];
    const float* l1br       = (const float*)d_in[15];
    const float* l1wi       = (const float*)d_in[16];
    const float* l1bi       = (const float*)d_in[17];
    const float* l2wr       = (const float*)d_in[18];
    const float* l2br       = (const float*)d_in[19];
    const float* l2wi       = (const float*)d_in[20];
    const float* l2bi       = (const float*)d_in[21];
    const float* n1_gr      = (const float*)d_in[22];
    const float* n1_br      = (const float*)d_in[23];
    const float* n1_gi      = (const float*)d_in[24];
    const float* n1_bi      = (const float*)d_in[25];
    const float* n2_gr      = (const float*)d_in[26];
    const float* n2_br      = (const float*)d_in[27];
    const float* n2_gi      = (const float*)d_in[28];
    const float* n2_bi      = (const float*)d_in[29];

    float* out = (float*)d_out;
    float* out1 = out;
    float* out2 = out + (long)NB * LEN;

    float* W = nullptr;
    cudaGetSymbolAddress((void**)&W, gWS);

    float* F1T  = W + OF_F1;
    float* C2T  = W + OF_C2;
    float* FRM  = W + OF_FRAMES;
    float* SPEC = W + OF_SPEC;
    float* XR   = W + OF_XR;
    float* XI   = W + OF_XI;
    float* QKVR = W + OF_QKVR;
    float* QKVI = W + OF_QKVI;
    float* SC   = W + OF_SC;
    float* CB   = W + OF_CB;
    float* ORr  = W + OF_OR;
    float* OIi  = W + OF_OI;
    float* HR   = W + OF_HR;
    float* HI   = W + OF_HI;
    float* FRr  = W + OF_FR;
    float* FIi  = W + OF_FI;
    float* SP2  = W + OF_SP2;
    float* QP   = W + OF_QP;
    float* KP   = W + OF_KP;
    float* VT   = W + OF_VT;

    init_f1t<<<ceb(SZ_F1), 256>>>(F1T);
    init_c2t<<<ceb(SZ_C2), 256>>>(C2T, window);

    // STFT: SPEC[m][j] = sum_n FRM[m][n] * F1T[j][n]
    frames_k<<<ceb(SZ_FRAMES), 256>>>(FRM, mix, window);
    gemm3(1, FRM, F1T, SPEC, nullptr, NBT, DMODEL, NFFT, NFFT, NFFT, DMODEL, 1.f, 0.f, 0, 0);

    prepx_k<<<ceb(SZ_X), 256>>>(XR, XI, SPEC, c1wr, c1br, c1wi, c1bi);

    // QKV
    gemm3(1, XR, attn_in_w, QKVR, attn_in_b, NM, 3 * DMODEL, DMODEL, DMODEL, DMODEL, 3 * DMODEL, 1.f, 1.f, 0, 0);
    gemm3(1, XI, attn_in_w, QKVI, attn_in_b, NM, 3 * DMODEL, DMODEL, DMODEL, DMODEL, 3 * DMODEL, 1.f, 1.f, 0, 0);

    repack_k<<<ceb(16L * TT * HDP), 256>>>(QKVR, QKVI, QP, KP, VT);

    // scores (tf32x3 — softmax IS sensitive to logit error)
    const float scl = 1.f / sqrtf((float)HD);
    const long sQ = (long)TT * HDP;
    const long sV = (long)HDP * TTP;
    const long nbs = (long)NB * SSQ;
    const float* QPr = QP; const float* QPi = QP + 8 * sQ;
    const float* KPr = KP; const float* KPi = KP + 8 * sQ;
    const float* VTr = VT; const float* VTi = VT + 8 * sV;
    gemm3(8, QPr, KPr, SC + 0 * nbs, nullptr, TT, TT, HD, HDP, HDP, TT, scl, 0.f, 0, 0, 2 * sQ, sQ, 2 * sQ, sQ, 2 * SSQ, SSQ);
    gemm3(8, QPr, KPi, SC + 1 * nbs, nullptr, TT, TT, HD, HDP, HDP, TT, scl, 0.f, 0, 0, 2 * sQ, sQ, 2 * sQ, sQ, 2 * SSQ, SSQ);
    gemm3(8, QPi, KPr, SC + 2 * nbs, nullptr, TT, TT, HD, HDP, HDP, TT, scl, 0.f, 0, 0, 2 * sQ, sQ, 2 * sQ, sQ, 2 * SSQ, SSQ);
    gemm3(8, QPi, KPi, SC + 3 * nbs, nullptr, TT, TT, HD, HDP, HDP, TT, scl, 0.f, 0, 0, 2 * sQ, sQ, 2 * sQ, sQ, 2 * SSQ, SSQ);

    softmax_k<<<4 * NB * TT, 256>>>(SC);
    combine_k<<<ceb(nbs), 256>>>(CB, SC);

    // AV: out_r = P@Vr + Q1@Vi ; out_i = P@Vi + Q2@Vr
    const long sCb = (long)TT * DMODEL, sCh = HD;
    gemm3(8, CB + 0 * nbs, VTr, XR, nullptr, TT, HD, TT, TT, TTP, DMODEL, 1.f, 0.f, 0, 0, 2 * SSQ, SSQ, 2 * sV, sV, sCb, sCh);
    gemm3(8, CB + 1 * nbs, VTi, XR, nullptr, TT, HD, TT, TT, TTP, DMODEL, 1.f, 0.f, 1, 0, 2 * SSQ, SSQ, 2 * sV, sV, sCb, sCh);
    gemm3(8, CB + 0 * nbs, VTi, XI, nullptr, TT, HD, TT, TT, TTP, DMODEL, 1.f, 0.f, 0, 0, 2 * SSQ, SSQ, 2 * sV, sV, sCb, sCh);
    gemm3(8, CB + 2 * nbs, VTr, XI, nullptr, TT, HD, TT, TT, TTP, DMODEL, 1.f, 0.f, 1, 0, 2 * SSQ, SSQ, 2 * sV, sV, sCb, sCh);

    // output projection
    gemm3(1, XR, attn_out_w, ORr, nullptr,    NM, DMODEL, DMODEL, DMODEL, DMODEL, DMODEL, 1.f, 0.f, 0, 0);
    gemm3(1, XI, attn_out_w, OIi, attn_out_b, NM, DMODEL, DMODEL, DMODEL, DMODEL, DMODEL, 1.f, 2.f, 0, 0);

    ln_k<<<NM, 256>>>(ORr, n1_gr, n1_br);
    ln_k<<<NM, 256>>>(OIi, n1_gi, n1_bi);

    // FFN layer 1 (+fused relu on accumulating second pass)
    gemm3(1, ORr, l1wr, HR, l1br, NM, DFF3, DMODEL, DMODEL, DMODEL, DFF3,  1.f,  1.f, 0, 0);
    gemm3(1, OIi, l1wi, HR, l1bi, NM, DFF3, DMODEL, DMODEL, DMODEL, DFF3, -1.f, -1.f, 1, 1);
    gemm3(1, OIi, l1wr, HI, l1br, NM, DFF3, DMODEL, DMODEL, DMODEL, DFF3,  1.f,  1.f, 0, 0);
    gemm3(1, ORr, l1wi, HI, l1bi, NM, DFF3, DMODEL, DMODEL, DMODEL, DFF3,  1.f,  1.f, 1, 1);

    // FFN layer 2
    gemm3(1, HR, l2wr, FRr, l2br, NM, DMODEL, DFF3, DFF3, DFF3, DMODEL,  1.f,  1.f, 0, 0);
    gemm3(1, HI, l2wi, FRr, l2bi, NM, DMODEL, DFF3, DFF3, DFF3, DMODEL, -1.f, -1.f, 1, 0);
    gemm3(1, HI, l2wr, FIi, l2br, NM, DMODEL, DFF3, DFF3, DFF3, DMODEL,  1.f,  1.f, 0, 0);
    gemm3(1, HR, l2wi, FIi, l2bi, NM, DMODEL, DFF3, DFF3, DFF3, DMODEL,  1.f,  1.f, 1, 0);

    ln_k<<<NM, 256>>>(FRr, n2_gr, n2_br);
    ln_k<<<NM, 256>>>(FIi, n2_gi, n2_bi);

    mask_k<<<ceb((long)NB * TT * BINS), 256>>>(FRr, FIi, SPEC, SP2, out2, c2wr, c2br, c2wi, c2bi);

    // iSTFT: FRM[m][n] = sum_j SP2[m][j] * C2T[n][j]
    gemm3(1, SP2, C2T, FRM, nullptr, NBT, NFFT, DMODEL, DMODEL, DMODEL, NFFT, 1.f, 0.f, 0, 0);
    ola_k<<<ceb((long)NB * LEN), 256>>>(FRM, window, out1);
}

// round 8
// speedup vs baseline: 1.7736x; 1.1919x over previous
#include <cuda_runtime.h>
#include <math.h>
#include <stdint.h>

// ---------------- constants ----------------
#define NFFT   2048
#define HOP    512
#define BINS   1025
#define DMODEL 2050
#define DFF3   8200
#define BATCH  4
#define LEN    441000
#define NB     8          // BATCH*2 signals
#define TT     862        // frames
#define NM     (BATCH*TT) // 3448 transformer rows
#define NBT    (NB*TT)    // 6896 stft rows
#define HD     1025       // head dim
#define HDP    1028       // padded head dim (mult of 4)
#define TTP    864        // padded TT
#define SSQ    ((long)TT*TT)

// ---------------- workspace layout ----------------
constexpr long SZ_F1     = (long)DMODEL*NFFT;   // F1T: [DMODEL][NFFT]
constexpr long SZ_C2     = (long)NFFT*DMODEL;   // C2T: [NFFT][DMODEL]
constexpr long SZ_FRAMES = (long)NBT*NFFT;
constexpr long SZ_SPEC   = (long)NBT*DMODEL;
constexpr long SZ_X      = (long)NM*DMODEL;
constexpr long SZ_QKV    = (long)NM*3*DMODEL;
constexpr long SZ_SC     = 4L*NB*SSQ;
constexpr long SZ_CB     = 3L*NB*SSQ;
constexpr long SZ_H      = (long)NM*DFF3;
constexpr long SZ_QP     = 16L*TT*HDP;
constexpr long SZ_VT     = 16L*HDP*TTP;
constexpr long SZ_TAB    = 4096;                // cos/sin tables (2048 each)

constexpr long OF_F1     = 0;
constexpr long OF_C2     = OF_F1 + SZ_F1;
constexpr long OF_FRAMES = OF_C2 + SZ_C2;
constexpr long OF_SPEC   = OF_FRAMES + SZ_FRAMES;
constexpr long OF_XR     = OF_SPEC + SZ_SPEC;
constexpr long OF_XI     = OF_XR + SZ_X;
constexpr long OF_QKVR   = OF_XI + SZ_X;
constexpr long OF_QKVI   = OF_QKVR + SZ_QKV;
constexpr long OF_SC     = OF_QKVI + SZ_QKV;
constexpr long OF_CB     = OF_SC + SZ_SC;
constexpr long OF_OR     = OF_CB + SZ_CB;
constexpr long OF_OI     = OF_OR + SZ_X;
constexpr long OF_HR     = OF_OI + SZ_X;
constexpr long OF_HI     = OF_HR + SZ_H;
constexpr long OF_FR     = OF_HI + SZ_H;
constexpr long OF_FI     = OF_FR + SZ_X;
constexpr long OF_SP2    = OF_FI + SZ_X;
constexpr long OF_QP     = OF_SP2 + SZ_SPEC;
constexpr long OF_KP     = OF_QP + SZ_QP;
constexpr long OF_VT     = OF_KP + SZ_QP;
constexpr long OF_T3     = OF_VT + SZ_VT;
constexpr long OF_SUMB   = OF_T3 + SZ_H;
constexpr long OF_TAB    = OF_SUMB + SZ_H;
constexpr long WS_TOTAL  = OF_TAB + SZ_TAB;

__device__ __align__(256) float gWS[WS_TOTAL];

// ---------------- helpers ----------------
__device__ __forceinline__ void mma8(float* c, const unsigned* a, const unsigned* b) {
    asm volatile(
        "mma.sync.aligned.m16n8k8.row.col.f32.tf32.tf32.f32 "
        "{%0,%1,%2,%3},{%4,%5,%6,%7},{%8,%9},{%0,%1,%2,%3};\n"
        : "+f"(c[0]), "+f"(c[1]), "+f"(c[2]), "+f"(c[3])
        : "r"(a[0]), "r"(a[1]), "r"(a[2]), "r"(a[3]),
          "r"(b[0]), "r"(b[1]));
}

// hi = x with low 13 mantissa bits zeroed (valid tf32, 1 LOP3);
// lo = x - hi (exact FADD; HW mma truncates lo's low bits -> ~2^-21 rel err)
#define TFMASK 0xFFFFE000u

// ---------------- tf32x3 tensor GEMM (raw-fp32 smem, mask-split in regs) ----
// TB form: C[M,N] = alpha * A[M,K] @ B[N,K]^T (+bias_scale*bias) (+C) (relu)
#define TW 20                    // padded tile row width (words)

__global__ void __launch_bounds__(256, 2) gemm_mma_k(
    const float* __restrict__ A, const float* __restrict__ B,
    float* __restrict__ C, const float* __restrict__ bias,
    int M, int N, int K, int lda, int ldb, int ldc,
    float alpha, float bias_scale, int accumulate, int relu,
    long sA0, long sA1, long sB0, long sB1, long sC0, long sC1)
{
    __shared__ float As[2][128][TW];
    __shared__ float Bs[2][128][TW];

    int z = blockIdx.z;
    A += (long)(z >> 1) * sA0 + (long)(z & 1) * sA1;
    B += (long)(z >> 1) * sB0 + (long)(z & 1) * sB1;
    C += (long)(z >> 1) * sC0 + (long)(z & 1) * sC1;

    const int tid  = threadIdx.x;
    const int lane = tid & 31;
    const int warp = tid >> 5;
    const int wm   = (warp >> 2) * 64;    // 0 / 64
    const int wn   = (warp & 3) * 32;     // 0..96
    const int row0 = blockIdx.y * 128;
    const int col0 = blockIdx.x * 128;

    const int lk = (tid & 7) * 2;         // k within stage (even)
    const int lr = tid >> 3;              // 0..31

    float c[4][4][4];
#pragma unroll
    for (int i = 0; i < 4; i++)
#pragma unroll
        for (int j = 0; j < 4; j++)
#pragma unroll
            for (int q = 0; q < 4; q++) c[i][j][q] = 0.f;

    auto ld2 = [&](const float* P, int R, int ld, int gr, int gk) {
        float2 v = make_float2(0.f, 0.f);
        if (gr < R) {
            long o = (long)gr * ld + gk;
            if (gk + 1 < K) v = *(const float2*)(P + o);
            else if (gk < K) v.x = P[o];
        }
        return v;
    };

    // prologue: stage 0
#pragma unroll
    for (int i = 0; i < 4; i++) {
        int m = lr + 32 * i;
        *(float2*)&As[0][m][lk] = ld2(A, M, lda, row0 + m, lk);
        *(float2*)&Bs[0][m][lk] = ld2(B, N, ldb, col0 + m, lk);
    }
    __syncthreads();

    int buf = 0;
    for (int k0 = 0; k0 < K; k0 += 16) {
        float2 pa[4], pb[4];
        const bool nxt = (k0 + 16 < K);
        if (nxt) {
            int kg = k0 + 16 + lk;
#pragma unroll
            for (int i = 0; i < 4; i++) {
                int m = lr + 32 * i;
                pa[i] = ld2(A, M, lda, row0 + m, kg);
                pb[i] = ld2(B, N, ldb, col0 + m, kg);
            }
        }

#pragma unroll
        for (int ks = 0; ks < 2; ks++) {
            const int ra = lane >> 2;
            const int kc = ks * 8 + (lane & 3);
            unsigned bh[4][2], bl[4][2];
#pragma unroll
            for (int ni = 0; ni < 4; ni++) {
                int n = wn + ni * 8 + ra;
                float b0 = Bs[buf][n][kc];
                float b1 = Bs[buf][n][kc + 4];
                unsigned h0 = __float_as_uint(b0) & TFMASK;
                unsigned h1 = __float_as_uint(b1) & TFMASK;
                bh[ni][0] = h0;
                bh[ni][1] = h1;
                bl[ni][0] = __float_as_uint(b0 - __uint_as_float(h0));
                bl[ni][1] = __float_as_uint(b1 - __uint_as_float(h1));
            }
#pragma unroll
            for (int mi = 0; mi < 4; mi++) {
                int r = wm + mi * 16 + ra;
                float a0 = As[buf][r][kc];
                float a1 = As[buf][r + 8][kc];
                float a2 = As[buf][r][kc + 4];
                float a3 = As[buf][r + 8][kc + 4];
                unsigned ah[4], al[4];
                ah[0] = __float_as_uint(a0) & TFMASK;
                ah[1] = __float_as_uint(a1) & TFMASK;
                ah[2] = __float_as_uint(a2) & TFMASK;
                ah[3] = __float_as_uint(a3) & TFMASK;
                al[0] = __float_as_uint(a0 - __uint_as_float(ah[0]));
                al[1] = __float_as_uint(a1 - __uint_as_float(ah[1]));
                al[2] = __float_as_uint(a2 - __uint_as_float(ah[2]));
                al[3] = __float_as_uint(a3 - __uint_as_float(ah[3]));
#pragma unroll
                for (int ni = 0; ni < 4; ni++) {
                    mma8(c[mi][ni], ah, bl[ni]);   // hi*lo
                    mma8(c[mi][ni], al, bh[ni]);   // lo*hi
                    mma8(c[mi][ni], ah, bh[ni]);   // hi*hi
                }
            }
        }

        if (nxt) {
            int b2 = buf ^ 1;
#pragma unroll
            for (int i = 0; i < 4; i++) {
                int m = lr + 32 * i;
                *(float2*)&As[b2][m][lk] = pa[i];
                *(float2*)&Bs[b2][m][lk] = pb[i];
            }
            __syncthreads();
            buf ^= 1;
        }
    }

    // epilogue
#pragma unroll
    for (int mi = 0; mi < 4; mi++) {
        int rbase = row0 + wm + mi * 16 + (lane >> 2);
#pragma unroll
        for (int ni = 0; ni < 4; ni++) {
            int cbase = col0 + wn + ni * 8 + 2 * (lane & 3);
#pragma unroll
            for (int q = 0; q < 4; q++) {
                int r = rbase + ((q >= 2) ? 8 : 0);
                int cc = cbase + (q & 1);
                if (r < M && cc < N) {
                    float v = alpha * c[mi][ni][q];
                    if (bias) v += bias_scale * bias[cc];
                    long o = (long)r * ldc + cc;
                    if (accumulate) v += C[o];
                    if (relu) v = fmaxf(v, 0.f);
                    C[o] = v;
                }
            }
        }
    }
}

// ---------------- trig tables (double precision, computed once) ----------------
__global__ void tab_k(float* __restrict__ tab) {
    int m = blockIdx.x * blockDim.x + threadIdx.x;
    if (m >= NFFT) return;
    double a = 6.283185307179586 * (double)m / (double)NFFT;
    tab[m]        = (float)cos(a);
    tab[m + NFFT] = (float)sin(a);
}

// ---------------- DFT matrix init (TB layouts, table lookups) ----------------
__global__ void init_f1t(float* __restrict__ F1, const float* __restrict__ tab) {
    long i = (long)blockIdx.x * blockDim.x + threadIdx.x;
    if (i >= SZ_F1) return;
    int j = (int)(i / NFFT), n = (int)(i % NFFT);
    int k = j >> 1;
    int m = (n * k) & (NFFT - 1);
    F1[i] = (j & 1) ? -tab[m + NFFT] : tab[m];
}

__global__ void init_c2t(float* __restrict__ C2, const float* __restrict__ tab,
                         const float* __restrict__ win) {
    long i = (long)blockIdx.x * blockDim.x + threadIdx.x;
    if (i >= SZ_C2) return;
    int n = (int)(i / DMODEL), j = (int)(i % DMODEL);
    int k = j >> 1;
    int m = (n * k) & (NFFT - 1);
    float tv = (j & 1) ? -tab[m + NFFT] : tab[m];
    float w = (k == 0 || k == BINS - 1) ? (1.0f / NFFT) : (2.0f / NFFT);  // exact powers of 2
    C2[i] = tv * w * win[n];
}

// ---------------- framing (reflect pad + window) ----------------
__global__ void frames_k(float* __restrict__ Fr, const float* __restrict__ mix,
                         const float* __restrict__ win) {
    long i = (long)blockIdx.x * blockDim.x + threadIdx.x;
    if (i >= SZ_FRAMES) return;
    int n = (int)(i & (NFFT - 1));
    long st = i >> 11;
    int t = (int)(st % TT);
    int s = (int)(st / TT);
    int gi = t * HOP + n;
    int j = gi - NFFT / 2;
    if (j < 0) j = -j;
    else if (j >= LEN) j = 2 * LEN - 2 - j;
    Fr[i] = mix[(long)s * LEN + j] * win[n];
}

// ---------------- conv1x1 + pos enc ----------------
__global__ void prepx_k(float* __restrict__ Xr, float* __restrict__ Xi,
                        const float* __restrict__ Spec,
                        const float* __restrict__ c1wr, const float* __restrict__ c1br,
                        const float* __restrict__ c1wi, const float* __restrict__ c1bi) {
    long i = (long)blockIdx.x * blockDim.x + threadIdx.x;
    if (i >= SZ_X) return;
    int d = (int)(i % DMODEL);
    long bt = i / DMODEL;
    int t = (int)(bt % TT);
    int b = (int)(bt / TT);
    int k = d >> 1, c = d & 1;
    long sp = ((long)(b * 2 + c) * TT + t) * DMODEL + 2 * k;
    float re = Spec[sp], im = Spec[sp + 1];
    float wr = c1wr[c], br = c1br[c], wi = c1wi[c], bi = c1bi[c];
    float nr = (re * wr + br) - (im * wi + bi);
    float ni = (im * wr + br) + (re * wi + bi);
    double freq = exp(-(double)(2 * k) * 9.210340371976184 / 2050.0);
    double arg = (double)t * freq;
    float pe = (d & 1) ? (float)cos(arg) : (float)sin(arg);
    Xr[i] = nr + pe;
    Xi[i] = ni + pe;
}

// ---------------- repack QKV into padded per-head buffers ----------------
__global__ void repack_k(const float* __restrict__ QKVr, const float* __restrict__ QKVi,
                         float* __restrict__ Qp, float* __restrict__ Kp, float* __restrict__ Vt) {
    long i = (long)blockIdx.x * blockDim.x + threadIdx.x;
    long tot = 16L * TT * HDP;
    if (i >= tot) return;
    int d = (int)(i % HDP);
    long rem = i / HDP;
    int t = (int)(rem % TT);
    int bh = (int)((rem / TT) & 7);
    int ri = (int)(rem / (TT * 8));
    const float* src = ri ? QKVi : QKVr;
    int b = bh >> 1, h = bh & 1;
    float q = 0.f, k = 0.f, v = 0.f;
    if (d < HD) {
        long o = ((long)(b * TT + t)) * (3 * DMODEL) + h * HD + d;
        q = src[o]; k = src[o + DMODEL]; v = src[o + 2 * DMODEL];
    }
    Qp[i] = q; Kp[i] = k;
    long vo = (((long)ri * 8 + bh) * HDP + d) * TTP + t;
    Vt[vo] = v;
}

// ---------------- softmax rows of length TT ----------------
__global__ void softmax_k(float* __restrict__ S) {
    long row = blockIdx.x;
    float* p = S + row * (long)TT;
    __shared__ float red[256];
    int tid = threadIdx.x;
    float m = -1e30f;
    for (int c = tid; c < TT; c += 256) m = fmaxf(m, p[c]);
    red[tid] = m; __syncthreads();
    for (int s = 128; s > 0; s >>= 1) { if (tid < s) red[tid] = fmaxf(red[tid], red[tid + s]); __syncthreads(); }
    m = red[0];
    __syncthreads();
    float sum = 0.f;
    for (int c = tid; c < TT; c += 256) { float e = __expf(p[c] - m); p[c] = e; sum += e; }
    red[tid] = sum; __syncthreads();
    for (int s = 128; s > 0; s >>= 1) { if (tid < s) red[tid] += red[tid + s]; __syncthreads(); }
    float inv = 1.f / red[0];
    for (int c = tid; c < TT; c += 256) p[c] *= inv;
}

__global__ void combine_k(float* __restrict__ CB, const float* __restrict__ SC) {
    long i = (long)blockIdx.x * blockDim.x + threadIdx.x;
    long n = (long)NB * SSQ;
    if (i >= n) return;
    float arr = SC[i], ari = SC[i + n], air = SC[i + 2 * n], aii = SC[i + 3 * n];
    CB[i]         = arr - aii;
    CB[i + n]     = ari - air;
    CB[i + 2 * n] = ari + air;
}

__global__ void ln_k(float* __restrict__ X, const float* __restrict__ g, const float* __restrict__ b) {
    long row = blockIdx.x;
    float* p = X + row * (long)DMODEL;
    __shared__ float red[256];
    int tid = threadIdx.x;
    float s = 0.f;
    for (int c = tid; c < DMODEL; c += 256) s += p[c];
    red[tid] = s; __syncthreads();
    for (int k = 128; k > 0; k >>= 1) { if (tid < k) red[tid] += red[tid + k]; __syncthreads(); }
    float mean = red[0] / (float)DMODEL;
    __syncthreads();
    float v = 0.f;
    for (int c = tid; c < DMODEL; c += 256) { float d = p[c] - mean; v += d * d; }
    red[tid] = v; __syncthreads();
    for (int k = 128; k > 0; k >>= 1) { if (tid < k) red[tid] += red[tid + k]; __syncthreads(); }
    float inv = rsqrtf(red[0] / (float)DMODEL + 1e-5f);
    for (int c = tid; c < DMODEL; c += 256) p[c] = (p[c] - mean) * inv * g[c] + b[c];
}

// ---------------- elementwise add (Karatsuba prep) ----------------
__global__ void add_k(float* __restrict__ dst, const float* __restrict__ a,
                      const float* __restrict__ b, long n) {
    long i = (long)blockIdx.x * blockDim.x + threadIdx.x;
    if (i < n) dst[i] = a[i] + b[i];
}

// Karatsuba combine: T1 (in buf1), T2 (in buf2), T3.
// buf1 <- t1 - t2 + (br - bi)  [relu]
// buf2 <- t3 - t1 - t2 + (br + bi)  [relu]
template <int RELU, int NCOL>
__global__ void kcomb_k(float* __restrict__ buf1, float* __restrict__ buf2,
                        const float* __restrict__ T3,
                        const float* __restrict__ br, const float* __restrict__ bi,
                        long n) {
    long i = (long)blockIdx.x * blockDim.x + threadIdx.x;
    if (i >= n) return;
    int col = (int)(i % NCOL);
    float t1 = buf1[i], t2 = buf2[i], t3 = T3[i];
    float bR = br[col], bI = bi[col];
    float re = t1 - t2 + (bR - bI);
    float im = t3 - t1 - t2 + (bR + bI);
    if (RELU) { re = fmaxf(re, 0.f); im = fmaxf(im, 0.f); }
    buf1[i] = re;
    buf2[i] = im;
}

__global__ void mask_k(const float* __restrict__ Fr_, const float* __restrict__ Fi_,
                       const float* __restrict__ Spec, float* __restrict__ Sp2,
                       float* __restrict__ out2,
                       const float* __restrict__ c2wr, const float* __restrict__ c2br,
                       const float* __restrict__ c2wi, const float* __restrict__ c2bi) {
    long i = (long)blockIdx.x * blockDim.x + threadIdx.x;
    long tot = (long)NB * TT * BINS;
    if (i >= tot) return;
    int k = (int)(i % BINS);
    long st = i / BINS;
    int t = (int)(st % TT);
    int s = (int)(st / TT);
    int b = s >> 1, c = s & 1;
    long xo = ((long)b * TT + t) * DMODEL + 2 * k + c;
    float nr = Fr_[xo], ni = Fi_[xo];
    float mr = (nr * c2wr[c] + c2br[c]) - (ni * c2wi[c] + c2bi[c]);
    float mi = (ni * c2wr[c] + c2br[c]) + (nr * c2wi[c] + c2bi[c]);
    long sp = ((long)s * TT + t) * DMODEL + 2 * k;
    float re = Spec[sp]     * (1.f / (1.f + __expf(-mr)));
    float im = Spec[sp + 1] * (1.f / (1.f + __expf(-mi)));
    Sp2[sp] = re; Sp2[sp + 1] = im;
    long o2 = (((long)s * BINS + k) * TT + t) * 2;
    out2[o2] = re; out2[o2 + 1] = im;
}

__global__ void ola_k(const float* __restrict__ Frm, const float* __restrict__ win,
                      float* __restrict__ out1) {
    long i = (long)blockIdx.x * blockDim.x + threadIdx.x;
    long tot = (long)NB * LEN;
    if (i >= tot) return;
    int x = (int)(i % LEN);
    int s = (int)(i / LEN);
    int gi = x + NFFT / 2;
    float acc = 0.f, wsq = 0.f;
    int tmax = gi / HOP; if (tmax > TT - 1) tmax = TT - 1;
    for (int t = tmax; t >= 0; --t) {
        int n = gi - t * HOP;
        if (n >= NFFT) break;
        acc += Frm[((long)s * TT + t) * NFFT + n];
        float w = win[n];
        wsq += w * w;
    }
    out1[i] = acc / (wsq > 1e-11f ? wsq : 1.f);
}

// ---------------- host helpers ----------------
static inline unsigned ceb(long n) { return (unsigned)((n + 255) / 256); }

static void gemm3(int Z, const float* A, const float* B, float* C, const float* bias,
                  int M, int N, int K, int lda, int ldb, int ldc,
                  float alpha, float bscale, int acc, int relu,
                  long a0 = 0, long a1 = 0, long b0 = 0, long b1 = 0, long c0 = 0, long c1 = 0)
{
    dim3 g((unsigned)((N + 127) / 128), (unsigned)((M + 127) / 128), (unsigned)Z);
    gemm_mma_k<<<g, 256>>>(A, B, C, bias, M, N, K, lda, ldb, ldc,
                           alpha, bscale, acc, relu, a0, a1, b0, b1, c0, c1);
}

extern "C" void kernel_launch(void* const* d_in, const int* in_sizes, int n_in,
                              void* d_out, int out_size) {
    const float* mix        = (const float*)d_in[0];
    const float* window     = (const float*)d_in[1];
    const float* c1wr       = (const float*)d_in[2];
    const float* c1br       = (const float*)d_in[3];
    const float* c1wi       = (const float*)d_in[4];
    const float* c1bi       = (const float*)d_in[5];
    const float* c2wr       = (const float*)d_in[6];
    const float* c2br       = (const float*)d_in[7];
    const float* c2wi       = (const float*)d_in[8];
    const float* c2bi       = (const float*)d_in[9];
    const float* attn_in_w  = (const float*)d_in[10];
    const float* attn_in_b  = (const float*)d_in[11];
    const float* attn_out_w = (const float*)d_in[12];
    const float* attn_out_b = (const float*)d_in[13];
    const float* l1wr       = (const float*)d_in[14];
    const float* l1br       = (const float*)d_in[15];
    const float* l1wi       = (const float*)d_in[16];
    const float* l1bi       = (const float*)d_in[17];
    const float* l2wr       = (const float*)d_in[18];
    const float* l2br       = (const float*)d_in[19];
    const float* l2wi       = (const float*)d_in[20];
    const float* l2bi       = (const float*)d_in[21];
    const float* n1_gr      = (const float*)d_in[22];
    const float* n1_br      = (const float*)d_in[23];
    const float* n1_gi      = (const float*)d_in[24];
    const float* n1_bi      = (const float*)d_in[25];
    const float* n2_gr      = (const float*)d_in[26];
    const float* n2_br      = (const float*)d_in[27];
    const float* n2_gi      = (const float*)d_in[28];
    const float* n2_bi      = (const float*)d_in[29];

    float* out = (float*)d_out;
    float* out1 = out;
    float* out2 = out + (long)NB * LEN;

    float* W = nullptr;
    cudaGetSymbolAddress((void**)&W, gWS);

    float* F1T  = W + OF_F1;
    float* C2T  = W + OF_C2;
    float* FRM  = W + OF_FRAMES;
    float* SPEC = W + OF_SPEC;
    float* XR   = W + OF_XR;
    float* XI   = W + OF_XI;
    float* QKVR = W + OF_QKVR;
    float* QKVI = W + OF_QKVI;
    float* SC   = W + OF_SC;
    float* CB   = W + OF_CB;
    float* ORr  = W + OF_OR;
    float* OIi  = W + OF_OI;
    float* HR   = W + OF_HR;
    float* HI   = W + OF_HI;
    float* FRr  = W + OF_FR;
    float* FIi  = W + OF_FI;
    float* SP2  = W + OF_SP2;
    float* QP   = W + OF_QP;
    float* KP   = W + OF_KP;
    float* VT   = W + OF_VT;
    float* T3   = W + OF_T3;
    float* SUMB = W + OF_SUMB;
    float* TAB  = W + OF_TAB;

    tab_k<<<(NFFT + 255) / 256, 256>>>(TAB);
    init_f1t<<<ceb(SZ_F1), 256>>>(F1T, TAB);
    init_c2t<<<ceb(SZ_C2), 256>>>(C2T, TAB, window);

    // STFT: SPEC[m][j] = sum_n FRM[m][n] * F1T[j][n]
    frames_k<<<ceb(SZ_FRAMES), 256>>>(FRM, mix, window);
    gemm3(1, FRM, F1T, SPEC, nullptr, NBT, DMODEL, NFFT, NFFT, NFFT, DMODEL, 1.f, 0.f, 0, 0);

    prepx_k<<<ceb(SZ_X), 256>>>(XR, XI, SPEC, c1wr, c1br, c1wi, c1bi);

    // QKV (same real weight for r and i streams)
    gemm3(1, XR, attn_in_w, QKVR, attn_in_b, NM, 3 * DMODEL, DMODEL, DMODEL, DMODEL, 3 * DMODEL, 1.f, 1.f, 0, 0);
    gemm3(1, XI, attn_in_w, QKVI, attn_in_b, NM, 3 * DMODEL, DMODEL, DMODEL, DMODEL, 3 * DMODEL, 1.f, 1.f, 0, 0);

    repack_k<<<ceb(16L * TT * HDP), 256>>>(QKVR, QKVI, QP, KP, VT);

    // scores (tf32x3 — softmax IS sensitive to logit error)
    const float scl = 1.f / sqrtf((float)HD);
    const long sQ = (long)TT * HDP;
    const long sV = (long)HDP * TTP;
    const long nbs = (long)NB * SSQ;
    const float* QPr = QP; const float* QPi = QP + 8 * sQ;
    const float* KPr = KP; const float* KPi = KP + 8 * sQ;
    const float* VTr = VT; const float* VTi = VT + 8 * sV;
    gemm3(8, QPr, KPr, SC + 0 * nbs, nullptr, TT, TT, HD, HDP, HDP, TT, scl, 0.f, 0, 0, 2 * sQ, sQ, 2 * sQ, sQ, 2 * SSQ, SSQ);
    gemm3(8, QPr, KPi, SC + 1 * nbs, nullptr, TT, TT, HD, HDP, HDP, TT, scl, 0.f, 0, 0, 2 * sQ, sQ, 2 * sQ, sQ, 2 * SSQ, SSQ);
    gemm3(8, QPi, KPr, SC + 2 * nbs, nullptr, TT, TT, HD, HDP, HDP, TT, scl, 0.f, 0, 0, 2 * sQ, sQ, 2 * sQ, sQ, 2 * SSQ, SSQ);
    gemm3(8, QPi, KPi, SC + 3 * nbs, nullptr, TT, TT, HD, HDP, HDP, TT, scl, 0.f, 0, 0, 2 * sQ, sQ, 2 * sQ, sQ, 2 * SSQ, SSQ);

    softmax_k<<<4 * NB * TT, 256>>>(SC);
    combine_k<<<ceb(nbs), 256>>>(CB, SC);

    // AV: out_r = P@Vr + Q1@Vi ; out_i = P@Vi + Q2@Vr
    const long sCb = (long)TT * DMODEL, sCh = HD;
    gemm3(8, CB + 0 * nbs, VTr, XR, nullptr, TT, HD, TT, TT, TTP, DMODEL, 1.f, 0.f, 0, 0, 2 * SSQ, SSQ, 2 * sV, sV, sCb, sCh);
    gemm3(8, CB + 1 * nbs, VTi, XR, nullptr, TT, HD, TT, TT, TTP, DMODEL, 1.f, 0.f, 1, 0, 2 * SSQ, SSQ, 2 * sV, sV, sCb, sCh);
    gemm3(8, CB + 0 * nbs, VTi, XI, nullptr, TT, HD, TT, TT, TTP, DMODEL, 1.f, 0.f, 0, 0, 2 * SSQ, SSQ, 2 * sV, sV, sCb, sCh);
    gemm3(8, CB + 2 * nbs, VTr, XI, nullptr, TT, HD, TT, TT, TTP, DMODEL, 1.f, 0.f, 1, 0, 2 * SSQ, SSQ, 2 * sV, sV, sCb, sCh);

    // output projection (real weight)
    gemm3(1, XR, attn_out_w, ORr, nullptr,    NM, DMODEL, DMODEL, DMODEL, DMODEL, DMODEL, 1.f, 0.f, 0, 0);
    gemm3(1, XI, attn_out_w, OIi, attn_out_b, NM, DMODEL, DMODEL, DMODEL, DMODEL, DMODEL, 1.f, 2.f, 0, 0);

    ln_k<<<NM, 256>>>(ORr, n1_gr, n1_br);
    ln_k<<<NM, 256>>>(OIi, n1_gi, n1_bi);

    // ---- FFN layer 1, Karatsuba (3 GEMMs instead of 4) ----
    // t1 = ORr@Wr -> HR ; t2 = OIi@Wi -> HI ; t3 = (ORr+OIi)@(Wr+Wi) -> T3
    // HR = relu(t1 - t2 + br - bi) ; HI = relu(t3 - t1 - t2 + br + bi)
    add_k<<<ceb(SZ_X), 256>>>(XR, ORr, OIi, SZ_X);                    // XR free; reuse as row-sum
    add_k<<<ceb((long)DFF3 * DMODEL), 256>>>(SC, l1wr, l1wi, (long)DFF3 * DMODEL);  // SC free; W1 sum
    gemm3(1, ORr, l1wr, HR, nullptr, NM, DFF3, DMODEL, DMODEL, DMODEL, DFF3, 1.f, 0.f, 0, 0);
    gemm3(1, OIi, l1wi, HI, nullptr, NM, DFF3, DMODEL, DMODEL, DMODEL, DFF3, 1.f, 0.f, 0, 0);
    gemm3(1, XR,  SC,   T3, nullptr, NM, DFF3, DMODEL, DMODEL, DMODEL, DFF3, 1.f, 0.f, 0, 0);
    kcomb_k<1, DFF3><<<ceb(SZ_H), 256>>>(HR, HI, T3, l1br, l1bi, SZ_H);

    // ---- FFN layer 2, Karatsuba ----
    add_k<<<ceb(SZ_H), 256>>>(SUMB, HR, HI, SZ_H);
    add_k<<<ceb((long)DMODEL * DFF3), 256>>>(CB, l2wr, l2wi, (long)DMODEL * DFF3);  // CB free; W2 sum
    gemm3(1, HR,   l2wr, FRr, nullptr, NM, DMODEL, DFF3, DFF3, DFF3, DMODEL, 1.f, 0.f, 0, 0);
    gemm3(1, HI,   l2wi, FIi, nullptr, NM, DMODEL, DFF3, DFF3, DFF3, DMODEL, 1.f, 0.f, 0, 0);
    gemm3(1, SUMB, CB,   T3,  nullptr, NM, DMODEL, DFF3, DFF3, DFF3, DMODEL, 1.f, 0.f, 0, 0);
    kcomb_k<0, DMODEL><<<ceb(SZ_X), 256>>>(FRr, FIi, T3, l2br, l2bi, SZ_X);

    ln_k<<<NM, 256>>>(FRr, n2_gr, n2_br);
    ln_k<<<NM, 256>>>(FIi, n2_gi, n2_bi);

    mask_k<<<ceb((long)NB * TT * BINS), 256>>>(FRr, FIi, SPEC, SP2, out2, c2wr, c2br, c2wi, c2bi);

    // iSTFT: FRM[m][n] = sum_j SP2[m][j] * C2T[n][j]
    gemm3(1, SP2, C2T, FRM, nullptr, NBT, NFFT, DMODEL, DMODEL, DMODEL, NFFT, 1.f, 0.f, 0, 0);
    ola_k<<<ceb((long)NB * LEN), 256>>>(FRM, window, out1);
}